// round 4
// baseline (speedup 1.0000x reference)
#include <cuda_runtime.h>
#include <cstdint>
#include <math_constants.h>

#define SEQ        32768
#define NT         512
#define START_TAG  510
#define END_TAG    511
#define NEG_FILL   (-10000.0f)

#define NCTA_FWD   32
#define ROWS_PER_CTA 16          // 512 / 32, one row per warp
#define THREADS_FWD 512

#define CHUNKS     128
#define CHUNK_LEN  256           // 128 * 256 = 32768

// ---------------- scratch (__device__ globals are the sanctioned path) ----------------
__device__ __align__(16) float g_alphas[(size_t)(SEQ + 1) * NT];  // alpha_t, t=0..SEQ
__device__ unsigned char  g_bpc[(size_t)SEQ * NT];            // coarse backptr: winning 16-col block
__device__ unsigned short g_traj[(size_t)SEQ * NT];           // speculative chains: traj[t][v]
__device__ unsigned short g_G[CHUNKS * NT];                   // chunk composition maps
__device__ int            g_seeds[CHUNKS];                    // resolved chunk seeds
__device__ unsigned int   g_bar;                              // spin-barrier counter
__device__ int            g_markA;                            // fwd entered
__device__ int            g_markB;                            // #CTAs that finished fwd

// ================= reset: barrier counter + alpha_0 + diag ==============
__global__ void reset_kernel()
{
    const int i = threadIdx.x;
    if (i == 0) { g_bar = 0u; g_markA = 0; g_markB = 0; }
    g_alphas[i] = (i == START_TAG) ? 0.0f : NEG_FILL;
}

// ================= Forward: 32 persistent CTAs, spin barrier through L2 ==============
__global__ void fwd_kernel(const float* __restrict__ unary, const float* __restrict__ trans)
{
    const int tid = threadIdx.x;
    const int w   = tid >> 5;
    const int l   = tid & 31;
    const int row = (int)blockIdx.x * ROWS_PER_CTA + w;   // this warp owns one row

    if (blockIdx.x == 0 && tid == 0) g_markA = 1;         // diag: fwd entered

    // transition row into registers: lane l holds cols [16l, 16l+16)
    float tr[16];
    {
        const float4* tp = (const float4*)(trans + (size_t)row * NT + l * 16);
        #pragma unroll
        for (int k = 0; k < 4; k++) {
            float4 a = tp[k];
            tr[4*k] = a.x; tr[4*k+1] = a.y; tr[4*k+2] = a.z; tr[4*k+3] = a.w;
        }
    }

    float u_next = (l == 0) ? unary[(size_t)0 * NT + row] : 0.0f;

    for (int t = 0; t < SEQ; t++) {
        const float u_cur = u_next;
        if (l == 0 && t + 1 < SEQ) u_next = unary[(size_t)(t + 1) * NT + row];

        // this lane's 16 alphas
        float al[16];
        if (t == 0) {
            #pragma unroll
            for (int k = 0; k < 16; k++)
                al[k] = (l * 16 + k == START_TAG) ? 0.0f : NEG_FILL;
        } else {
            const float4* ap = (const float4*)(g_alphas + (size_t)t * NT + l * 16);
            float4 a0 = ap[0], a1 = ap[1], a2 = ap[2], a3 = ap[3];
            al[0]=a0.x; al[1]=a0.y; al[2]=a0.z;  al[3]=a0.w;
            al[4]=a1.x; al[5]=a1.y; al[6]=a1.z;  al[7]=a1.w;
            al[8]=a2.x; al[9]=a2.y; al[10]=a2.z; al[11]=a2.w;
            al[12]=a3.x;al[13]=a3.y;al[14]=a3.z; al[15]=a3.w;
        }

        float m = -CUDART_INF_F;
        #pragma unroll
        for (int k = 0; k < 16; k++) m = fmaxf(m, al[k] + tr[k]);
        float M = m;
        #pragma unroll
        for (int o = 16; o; o >>= 1) M = fmaxf(M, __shfl_xor_sync(0xffffffffu, M, o));
        unsigned bal = __ballot_sync(0xffffffffu, m == M);
        if (l == 0) {
            g_alphas[(size_t)(t + 1) * NT + row] = M + u_cur;   // bitwise == vit + u_t
            g_bpc[(size_t)t * NT + row] = (unsigned char)(__ffs(bal) - 1);
        }

        // ---- grid barrier: every thread publishes its own stores first ----
        __threadfence();
        __syncthreads();
        if (tid == 0) {
            atomicAdd(&g_bar, 1u);
            const unsigned target = (unsigned)(t + 1) * NCTA_FWD;
            while (*(volatile unsigned*)&g_bar < target) { }
            __threadfence();                       // acquire
        }
        __syncthreads();
    }

    if (tid == 0) atomicAdd(&g_markB, 1);          // diag: this CTA finished
}

// ================= Traceback ==============
// Exact refinement of one coarse backptr (matches jnp.argmax first-occurrence tie-break):
__device__ __forceinline__ int pm_step(int t, int u, const float* __restrict__ trans)
{
    const int base = (int)g_bpc[(size_t)t * NT + u] * 16;
    const float4* ap = (const float4*)(g_alphas + (size_t)t * NT + base);
    const float4* tp = (const float4*)(trans + (size_t)u * NT + base);
    float best = -CUDART_INF_F; int bj = 0;
    #pragma unroll
    for (int q = 0; q < 4; q++) {
        float4 a = ap[q], b = tp[q];
        float s;
        s = a.x + b.x; if (s > best) { best = s; bj = 4*q + 0; }
        s = a.y + b.y; if (s > best) { best = s; bj = 4*q + 1; }
        s = a.z + b.z; if (s > best) { best = s; bj = 4*q + 2; }
        s = a.w + b.w; if (s > best) { best = s; bj = 4*q + 3; }
    }
    return base + bj;
}

// Pass 1: per chunk, run all 512 speculative chains (one per possible exit tag).
__global__ void __launch_bounds__(NT) pass1_kernel(const float* __restrict__ trans)
{
    const int c  = blockIdx.x;
    const int v  = threadIdx.x;
    const int lo = c * CHUNK_LEN;
    const int hi = lo + CHUNK_LEN;
    int u = v;                              // hypothesis: path[hi-1] == v
    for (int t = hi - 1; t >= lo; t--) {
        g_traj[(size_t)t * NT + v] = (unsigned short)u;   // candidate path[t]
        u = pm_step(t, u, trans);
    }
    g_G[c * NT + v] = (unsigned short)u;    // candidate path[lo-1] -> seed of chunk c-1
}

// Pass 2: terminal argmax + serial composition of 128 chunk maps.
__global__ void __launch_bounds__(NT) pass2_kernel(const float* __restrict__ trans,
                                                   float* __restrict__ out, int out_size)
{
    __shared__ float sv[NT];
    __shared__ int   si[NT];
    const int i = threadIdx.x;
    float s = g_alphas[(size_t)SEQ * NT + i] + trans[(size_t)END_TAG * NT + i];
    sv[i] = s; si[i] = i;
    __syncthreads();
    for (int o = NT / 2; o; o >>= 1) {
        if (i < o) {
            float a = sv[i], b = sv[i + o];
            int   ia = si[i], ib = si[i + o];
            if (b > a || (b == a && ib < ia)) { sv[i] = b; si[i] = ib; }  // first-occurrence ties
        }
        __syncthreads();
    }
    if (i == 0) {
        int v = si[0];
        if (out_size > SEQ) out[SEQ] = sv[0];             // path_score (float32)
        g_seeds[CHUNKS - 1] = v;
        for (int c = CHUNKS - 1; c > 0; c--) {
            v = (int)g_G[c * NT + v];
            g_seeds[c - 1] = v;
        }
    }
}

// Pass 3: gather the real path (float32 output); diagnostics offset stays 0 when healthy.
__global__ void __launch_bounds__(256) pass3_kernel(float* __restrict__ out, int out_size)
{
    const int t = blockIdx.x * blockDim.x + threadIdx.x;
    if (t < SEQ && t < out_size) {
        float off = 0.0f;
        if (g_markA == 0)                 off = 100000.0f;   // fwd never started
        else if (g_markB < NCTA_FWD)      off = 300000.0f;   // fwd didn't finish
        else if (g_alphas[NT] == 0.0f)    off = 500000.0f;   // writes not visible
        int seed = g_seeds[t / CHUNK_LEN];
        out[t] = (float)g_traj[(size_t)t * NT + seed] + off;
    }
}

// ================= launch ==============
extern "C" void kernel_launch(void* const* d_in, const int* in_sizes, int n_in,
                              void* d_out, int out_size)
{
    const float* unary = (const float*)d_in[0];   // (32768, 1, 512) f32
    const float* trans = (const float*)d_in[1];   // (1, 512, 512)  f32
    (void)in_sizes; (void)n_in;

    float* out = (float*)d_out;

    reset_kernel<<<1, NT>>>();
    fwd_kernel  <<<NCTA_FWD, THREADS_FWD>>>(unary, trans);
    pass1_kernel<<<CHUNKS, NT>>>(trans);
    pass2_kernel<<<1, NT>>>(trans, out, out_size);
    pass3_kernel<<<SEQ / 256, 256>>>(out, out_size);
}

// round 5
// speedup vs baseline: 1.5132x; 1.5132x over previous
#include <cuda_runtime.h>
#include <cstdint>
#include <math_constants.h>

#define SEQ        32768
#define NT         512
#define START_TAG  510
#define END_TAG    511
#define NEG_FILL   (-10000.0f)

#define NCTA       8             // portable cluster size — guaranteed to launch
#define TPC        512           // threads per CTA (16 warps)
#define RPC        64            // rows per CTA
#define RPW        4             // rows per warp

#define CHUNKS     128
#define CHUNK_LEN  256           // 128 * 256 = 32768

// ---------------- scratch (__device__ globals are the sanctioned path) ----------------
__device__ __align__(16) float g_alphas[(size_t)(SEQ + 1) * NT];  // alpha_t, t=0..SEQ
__device__ unsigned char  g_bpc[(size_t)SEQ * NT];            // coarse backptr: winning 16-col block
__device__ unsigned short g_traj[(size_t)SEQ * NT];           // speculative chains: traj[t][v]
__device__ unsigned short g_G[CHUNKS * NT];                   // chunk composition maps
__device__ int            g_seeds[CHUNKS];                    // resolved chunk seeds
__device__ int            g_markB;                            // #CTAs that finished fwd (canary)

// ---------------- ptx helpers ----------------
__device__ __forceinline__ uint32_t s2u(const void* p) {
    uint32_t a;
    asm("{ .reg .u64 t; cvta.to.shared.u64 t, %1; cvt.u32.u64 %0, t; }" : "=r"(a) : "l"(p));
    return a;
}
__device__ __forceinline__ uint32_t mapa_u32(uint32_t a, uint32_t r) {
    uint32_t d;
    asm("mapa.shared::cluster.u32 %0, %1, %2;" : "=r"(d) : "r"(a), "r"(r));
    return d;
}
__device__ __forceinline__ void stc_f32(uint32_t a, float v) {
    asm volatile("st.shared::cluster.f32 [%0], %1;" :: "r"(a), "f"(v) : "memory");
}
__device__ __forceinline__ void cluster_sync_() {
    asm volatile("barrier.cluster.arrive.aligned;" ::: "memory");
    asm volatile("barrier.cluster.wait.aligned;" ::: "memory");
}
__device__ __forceinline__ uint32_t ctarank() {
    uint32_t r; asm("mov.u32 %0, %%cluster_ctarank;" : "=r"(r)); return r;
}

// ================= reset: alpha_0 + canary ==============
__global__ void reset_kernel()
{
    const int i = threadIdx.x;
    if (i == 0) g_markB = 0;
    g_alphas[i] = (i == START_TAG) ? 0.0f : NEG_FILL;
}

// ================= Forward: 8-CTA cluster, DSMEM push exchange ==============
__global__ void __cluster_dims__(NCTA, 1, 1) __launch_bounds__(TPC, 1)
fwd_kernel(const float* __restrict__ unary, const float* __restrict__ trans)
{
    __shared__ __align__(16) float abuf[2][NT];   // full alpha vector, double-buffered

    const int tid  = threadIdx.x;
    const int w    = tid >> 5;
    const int l    = tid & 31;
    const uint32_t rank = ctarank();
    const int r0   = (int)rank * RPC + w * RPW;   // warp owns rows r0..r0+3

    // transition rows in registers: lane l holds cols [16l, 16l+16) of 4 rows
    float tr[RPW][16];
    #pragma unroll
    for (int rr = 0; rr < RPW; rr++) {
        const float4* tp = (const float4*)(trans + (size_t)(r0 + rr) * NT + l * 16);
        #pragma unroll
        for (int k = 0; k < 4; k++) {
            float4 a = tp[k];
            tr[rr][4*k] = a.x; tr[rr][4*k+1] = a.y; tr[rr][4*k+2] = a.z; tr[rr][4*k+3] = a.w;
        }
    }

    // alpha_0 (every CTA holds the full vector locally)
    abuf[0][tid] = (tid == START_TAG) ? 0.0f : NEG_FILL;

    // scatter role: lane i pushes row r0+(i&3) to CTA (i>>2); address precomputed
    const uint32_t dst_base =
        mapa_u32(s2u(&abuf[0][0]) + (uint32_t)(r0 + (l & 3)) * 4u, (uint32_t)(l >> 2));

    // unary prefetch: lanes 0..3 hold u[t, r0+lane]
    float u_pref = (l < RPW) ? unary[r0 + l] : 0.0f;

    cluster_sync_();                      // abuf[0] ready everywhere

    int cur = 0;
    for (int t = 0; t < SEQ; t++) {
        // broadcast this step's unary values, then prefetch next step's
        const float u0 = __shfl_sync(0xffffffffu, u_pref, 0);
        const float u1 = __shfl_sync(0xffffffffu, u_pref, 1);
        const float u2 = __shfl_sync(0xffffffffu, u_pref, 2);
        const float u3 = __shfl_sync(0xffffffffu, u_pref, 3);
        if (l < RPW && t + 1 < SEQ) u_pref = unary[(size_t)(t + 1) * NT + r0 + l];

        // this lane's 16 alphas
        float al[16];
        {
            const float4* ap = (const float4*)&abuf[cur][l * 16];
            float4 a0 = ap[0], a1 = ap[1], a2 = ap[2], a3 = ap[3];
            al[0]=a0.x; al[1]=a0.y; al[2]=a0.z;  al[3]=a0.w;
            al[4]=a1.x; al[5]=a1.y; al[6]=a1.z;  al[7]=a1.w;
            al[8]=a2.x; al[9]=a2.y; al[10]=a2.z; al[11]=a2.w;
            al[12]=a3.x;al[13]=a3.y;al[14]=a3.z; al[15]=a3.w;
        }

        // 4 rows: per-lane partial maxes
        float m0 = -CUDART_INF_F, m1 = -CUDART_INF_F, m2 = -CUDART_INF_F, m3 = -CUDART_INF_F;
        #pragma unroll
        for (int k = 0; k < 16; k++) {
            m0 = fmaxf(m0, al[k] + tr[0][k]);
            m1 = fmaxf(m1, al[k] + tr[1][k]);
            m2 = fmaxf(m2, al[k] + tr[2][k]);
            m3 = fmaxf(m3, al[k] + tr[3][k]);
        }
        // butterfly reductions (all lanes end with the row max)
        float M0 = m0, M1 = m1, M2 = m2, M3 = m3;
        #pragma unroll
        for (int o = 16; o; o >>= 1) {
            M0 = fmaxf(M0, __shfl_xor_sync(0xffffffffu, M0, o));
            M1 = fmaxf(M1, __shfl_xor_sync(0xffffffffu, M1, o));
            M2 = fmaxf(M2, __shfl_xor_sync(0xffffffffu, M2, o));
            M3 = fmaxf(M3, __shfl_xor_sync(0xffffffffu, M3, o));
        }
        const unsigned b0 = __ballot_sync(0xffffffffu, m0 == M0);
        const unsigned b1 = __ballot_sync(0xffffffffu, m1 == M1);
        const unsigned b2 = __ballot_sync(0xffffffffu, m2 == M2);
        const unsigned b3 = __ballot_sync(0xffffffffu, m3 == M3);

        const float n0 = M0 + u0, n1 = M1 + u1, n2 = M2 + u2, n3 = M3 + u3;

        // lane's scatter value: n[l&3]
        const float va = (l & 1) ? n1 : n0;
        const float vb = (l & 1) ? n3 : n2;
        const float v  = (l & 2) ? vb : va;

        const int nxt = cur ^ 1;
        stc_f32(dst_base + (uint32_t)nxt * (NT * 4u), v);   // all 32 lanes: 8 CTAs x 4 rows

        // traceback state to global (lanes 0-3: alpha; lane 4: packed backptrs)
        if (l < RPW) g_alphas[(size_t)(t + 1) * NT + r0 + l] = v;
        if (l == 4) {
            unsigned bp = (unsigned)(__ffs(b0) - 1)
                        | ((unsigned)(__ffs(b1) - 1) << 8)
                        | ((unsigned)(__ffs(b2) - 1) << 16)
                        | ((unsigned)(__ffs(b3) - 1) << 24);
            *(unsigned*)&g_bpc[(size_t)t * NT + r0] = bp;
        }

        cluster_sync_();                  // publish DSMEM pushes cluster-wide
        cur = nxt;
    }

    if (tid == 0) atomicAdd(&g_markB, 1);  // canary
}

// ================= Traceback ==============
// Exact refinement of one coarse backptr (matches jnp.argmax first-occurrence tie-break):
__device__ __forceinline__ int pm_step(int t, int u, const float* __restrict__ trans)
{
    const int base = (int)g_bpc[(size_t)t * NT + u] * 16;
    const float4* ap = (const float4*)(g_alphas + (size_t)t * NT + base);
    const float4* tp = (const float4*)(trans + (size_t)u * NT + base);
    float best = -CUDART_INF_F; int bj = 0;
    #pragma unroll
    for (int q = 0; q < 4; q++) {
        float4 a = ap[q], b = tp[q];
        float s;
        s = a.x + b.x; if (s > best) { best = s; bj = 4*q + 0; }
        s = a.y + b.y; if (s > best) { best = s; bj = 4*q + 1; }
        s = a.z + b.z; if (s > best) { best = s; bj = 4*q + 2; }
        s = a.w + b.w; if (s > best) { best = s; bj = 4*q + 3; }
    }
    return base + bj;
}

// Pass 1: per chunk, run all 512 speculative chains (one per possible exit tag).
__global__ void __launch_bounds__(NT) pass1_kernel(const float* __restrict__ trans)
{
    const int c  = blockIdx.x;
    const int v  = threadIdx.x;
    const int lo = c * CHUNK_LEN;
    const int hi = lo + CHUNK_LEN;
    int u = v;                              // hypothesis: path[hi-1] == v
    for (int t = hi - 1; t >= lo; t--) {
        g_traj[(size_t)t * NT + v] = (unsigned short)u;   // candidate path[t]
        u = pm_step(t, u, trans);
    }
    g_G[c * NT + v] = (unsigned short)u;    // candidate path[lo-1] -> seed of chunk c-1
}

// Pass 2: terminal argmax + serial composition of 128 chunk maps.
__global__ void __launch_bounds__(NT) pass2_kernel(const float* __restrict__ trans,
                                                   float* __restrict__ out, int out_size)
{
    __shared__ float sv[NT];
    __shared__ int   si[NT];
    const int i = threadIdx.x;
    float s = g_alphas[(size_t)SEQ * NT + i] + trans[(size_t)END_TAG * NT + i];
    sv[i] = s; si[i] = i;
    __syncthreads();
    for (int o = NT / 2; o; o >>= 1) {
        if (i < o) {
            float a = sv[i], b = sv[i + o];
            int   ia = si[i], ib = si[i + o];
            if (b > a || (b == a && ib < ia)) { sv[i] = b; si[i] = ib; }  // first-occurrence ties
        }
        __syncthreads();
    }
    if (i == 0) {
        int v = si[0];
        if (out_size > SEQ) out[SEQ] = sv[0];             // path_score (float32)
        g_seeds[CHUNKS - 1] = v;
        for (int c = CHUNKS - 1; c > 0; c--) {
            v = (int)g_G[c * NT + v];
            g_seeds[c - 1] = v;
        }
    }
}

// Pass 3: gather the real path (float32 output); canary offset stays 0 when healthy.
__global__ void __launch_bounds__(256) pass3_kernel(float* __restrict__ out, int out_size)
{
    const int t = blockIdx.x * blockDim.x + threadIdx.x;
    if (t < SEQ && t < out_size) {
        float off = (g_markB < NCTA) ? 300000.0f : 0.0f;   // fwd didn't run/finish
        int seed = g_seeds[t / CHUNK_LEN];
        out[t] = (float)g_traj[(size_t)t * NT + seed] + off;
    }
}

// ================= launch ==============
extern "C" void kernel_launch(void* const* d_in, const int* in_sizes, int n_in,
                              void* d_out, int out_size)
{
    const float* unary = (const float*)d_in[0];   // (32768, 1, 512) f32
    const float* trans = (const float*)d_in[1];   // (1, 512, 512)  f32
    (void)in_sizes; (void)n_in;

    float* out = (float*)d_out;

    reset_kernel<<<1, NT>>>();
    fwd_kernel  <<<NCTA, TPC>>>(unary, trans);
    pass1_kernel<<<CHUNKS, NT>>>(trans);
    pass2_kernel<<<1, NT>>>(trans, out, out_size);
    pass3_kernel<<<SEQ / 256, 256>>>(out, out_size);
}